// round 3
// baseline (speedup 1.0000x reference)
#include <cuda_runtime.h>
#include <math.h>
#include <stdint.h>

// ---------------------------------------------------------------------------
// Problem constants
// ---------------------------------------------------------------------------
#define BATCH   256
#define DIM     384
#define KEY_DIM 32
#define HEADS   8
#define RES     14
#define NSP     196            // RES*RES
#define NH_KD   256            // KEY_DIM*HEADS
#define DV      128            // RATIO*KEY_DIM
#define DH      1024           // DV*HEADS
#define H_QKV   1536           // DH + 2*NH_KD
#define NTOT    (BATCH*NSP)    // 50176
#define EPS     1e-5f

// ---------------------------------------------------------------------------
// Scratch (device globals; allocation-free per harness rules)
// ---------------------------------------------------------------------------
__device__ float g_xT [DIM   * NTOT];
__device__ float g_qkv[H_QKV * NTOT];
__device__ float g_q  [NH_KD * NTOT];
__device__ float g_o  [DH    * NTOT];

__device__ __forceinline__ uint32_t f2tf32(float x) {
    uint32_t u;
    asm("cvt.rna.tf32.f32 %0, %1;" : "=r"(u) : "f"(x));
    return u;
}

#define MMA_TF32(D, A0, A1, A2, A3, B0, B1)                                    \
    asm volatile(                                                              \
        "mma.sync.aligned.m16n8k8.row.col.f32.tf32.tf32.f32 "                  \
        "{%0,%1,%2,%3}, {%4,%5,%6,%7}, {%8,%9}, {%0,%1,%2,%3};"                \
        : "+f"(D[0]), "+f"(D[1]), "+f"(D[2]), "+f"(D[3])                       \
        : "r"(A0), "r"(A1), "r"(A2), "r"(A3), "r"(B0), "r"(B1))

// ---------------------------------------------------------------------------
// K0: transpose x [B,384,196] -> xT [384, B*196]
// ---------------------------------------------------------------------------
__global__ void k_transpose(const float* __restrict__ x, float* __restrict__ xT) {
    int i = blockIdx.x * 256 + threadIdx.x;
    if (i >= DIM * NTOT) return;
    int n = i % NSP;
    int c = (i / NSP) % DIM;
    int b = i / (NSP * DIM);
    xT[c * NTOT + b * NSP + n] = x[i];
}

// ---------------------------------------------------------------------------
// TF32 tensor-core GEMM with fused BN epilogue (unchanged from R2).
// ---------------------------------------------------------------------------
#define GBM 128
#define GBN 128
#define GBK 32

__global__ __launch_bounds__(256) void k_gemm_tf32(
    const float* __restrict__ A, const float* __restrict__ B,
    float* __restrict__ C, int M, int N, int K,
    const float* __restrict__ gg, const float* __restrict__ bb,
    const float* __restrict__ mm, const float* __restrict__ vv,
    int scatter)
{
    __shared__ uint32_t As[GBM][GBK + 4];
    __shared__ uint32_t Bs[GBK][GBN + 8];

    const int tid  = threadIdx.x;
    const int lane = tid & 31;
    const int wid  = tid >> 5;
    const int wm   = wid & 1;
    const int wn   = wid >> 1;
    const int row0 = blockIdx.x * GBM;
    const int col0 = blockIdx.y * GBN;
    const int grp  = lane >> 2;
    const int tig  = lane & 3;

    float acc[4][4][4];
#pragma unroll
    for (int a = 0; a < 4; a++)
#pragma unroll
        for (int b = 0; b < 4; b++)
#pragma unroll
            for (int c = 0; c < 4; c++) acc[a][b][c] = 0.f;

    for (int k0 = 0; k0 < K; k0 += GBK) {
#pragma unroll
        for (int i = 0; i < 4; i++) {
            int s  = tid + i * 256;
            int r  = s >> 3;
            int kq = s & 7;
            float4 f = *(const float4*)&A[(size_t)(row0 + r) * K + k0 + kq * 4];
            uint4 t;
            t.x = f2tf32(f.x); t.y = f2tf32(f.y);
            t.z = f2tf32(f.z); t.w = f2tf32(f.w);
            *(uint4*)&As[r][kq * 4] = t;
        }
#pragma unroll
        for (int i = 0; i < 4; i++) {
            int s  = tid + i * 256;
            int kr = s >> 5;
            int nq = s & 31;
            float4 f = *(const float4*)&B[(size_t)(k0 + kr) * N + col0 + nq * 4];
            uint4 t;
            t.x = f2tf32(f.x); t.y = f2tf32(f.y);
            t.z = f2tf32(f.z); t.w = f2tf32(f.w);
            *(uint4*)&Bs[kr][nq * 4] = t;
        }
        __syncthreads();

#pragma unroll
        for (int ks = 0; ks < 4; ks++) {
            const int kb = ks * 8;
            uint32_t af[4][4], bf[4][2];
#pragma unroll
            for (int mf = 0; mf < 4; mf++) {
                int r = wm * 64 + mf * 16 + grp;
                af[mf][0] = As[r    ][kb + tig];
                af[mf][1] = As[r + 8][kb + tig];
                af[mf][2] = As[r    ][kb + tig + 4];
                af[mf][3] = As[r + 8][kb + tig + 4];
            }
#pragma unroll
            for (int nf = 0; nf < 4; nf++) {
                int c = wn * 32 + nf * 8 + grp;
                bf[nf][0] = Bs[kb + tig    ][c];
                bf[nf][1] = Bs[kb + tig + 4][c];
            }
#pragma unroll
            for (int mf = 0; mf < 4; mf++)
#pragma unroll
                for (int nf = 0; nf < 4; nf++)
                    MMA_TF32(acc[mf][nf], af[mf][0], af[mf][1], af[mf][2], af[mf][3],
                             bf[nf][0], bf[nf][1]);
        }
        __syncthreads();
    }

#pragma unroll
    for (int mf = 0; mf < 4; mf++) {
        int r0 = row0 + wm * 64 + mf * 16 + grp;
        int r1 = r0 + 8;
        float s0 = gg[r0] * rsqrtf(vv[r0] + EPS);
        float h0 = bb[r0] - mm[r0] * s0;
        float s1 = gg[r1] * rsqrtf(vv[r1] + EPS);
        float h1 = bb[r1] - mm[r1] * s1;
#pragma unroll
        for (int nf = 0; nf < 4; nf++) {
            int cc = col0 + wn * 32 + nf * 8 + tig * 2;
            float v00 = acc[mf][nf][0] * s0 + h0;
            float v01 = acc[mf][nf][1] * s0 + h0;
            float v10 = acc[mf][nf][2] * s1 + h1;
            float v11 = acc[mf][nf][3] * s1 + h1;
            if (scatter == 0) {
                *(float2*)&C[(size_t)r0 * N + cc] = make_float2(v00, v01);
                *(float2*)&C[(size_t)r1 * N + cc] = make_float2(v10, v11);
            } else {
                int b0i = cc / NSP,      sp0 = cc - b0i * NSP;
                int b1i = (cc+1) / NSP,  sp1 = (cc+1) - b1i * NSP;
                C[b0i * (DIM * NSP) + r0 * NSP + sp0] = v00;
                C[b1i * (DIM * NSP) + r0 * NSP + sp1] = v01;
                C[b0i * (DIM * NSP) + r1 * NSP + sp0] = v10;
                C[b1i * (DIM * NSP) + r1 * NSP + sp1] = v11;
            }
        }
    }
}

// ---------------------------------------------------------------------------
// K2: depthwise 3x3 conv on q + BN (unchanged)
// ---------------------------------------------------------------------------
__global__ void k_dwconv_bn(const float* __restrict__ qkv,
                            const float* __restrict__ w,
                            float* __restrict__ qout,
                            const float* __restrict__ gg, const float* __restrict__ bb,
                            const float* __restrict__ mm, const float* __restrict__ vv)
{
    int i = blockIdx.x * 256 + threadIdx.x;
    if (i >= NH_KD * NTOT) return;
    int sp = i % NSP;
    int b  = (i / NSP) % BATCH;
    int c  = i / NTOT;
    int y = sp / RES, x = sp % RES;

    const float* base = qkv + c * NTOT + b * NSP;
    const float* wc = w + c * 9;
    float acc = 0.f;
#pragma unroll
    for (int dy = -1; dy <= 1; dy++) {
        int yy = y + dy;
        if (yy < 0 || yy >= RES) continue;
#pragma unroll
        for (int dx = -1; dx <= 1; dx++) {
            int xx = x + dx;
            if (xx < 0 || xx >= RES) continue;
            acc = fmaf(wc[(dy + 1) * 3 + (dx + 1)], base[yy * RES + xx], acc);
        }
    }
    float s  = gg[c] * rsqrtf(vv[c] + EPS);
    float sh = bb[c] - mm[c] * s;
    qout[i] = acc * s + sh;
}

// ---------------------------------------------------------------------------
// K3: tensor-core attention.
//   Per (b,h) block: compute S^T = K^T(208x32) x Q(32x208q) via mma,
//   softmax over keys (xor-shuffle reductions), then O^T = V(128x208) x P^T
//   where P^T operand fragments come straight from S accumulators via shuffles.
//   416 threads = 13 warps; each warp owns two 8-query stripes (26 total).
// ---------------------------------------------------------------------------
#define ATTN_THREADS 416
#define QPITCH 216   // mod 32 = 24 -> B-frag loads conflict-free
#define KPITCH 36    // mod 32 = 4  -> A-frag loads conflict-free
#define VPITCH 212   // mod 32 = 20 -> A-frag loads conflict-free
#define QS_OFF 0
#define KS_OFF (32*QPITCH)              // 6912
#define VS_OFF (KS_OFF + 208*KPITCH)    // 14400
#define BS_OFF (VS_OFF + 128*VPITCH)    // 41536
#define ATTN_SMEM ((BS_OFF + 200)*4)    // 166,944 B

__global__ __launch_bounds__(ATTN_THREADS, 1) void k_attn(
    const float* __restrict__ qbuf, const float* __restrict__ qkv,
    const float* __restrict__ biases, const int* __restrict__ idxs,
    float* __restrict__ obuf)
{
    extern __shared__ float sm[];
    uint32_t* q_u = (uint32_t*)(sm + QS_OFF);   // [d=32][q 216]
    uint32_t* k_u = (uint32_t*)(sm + KS_OFF);   // [m=208][d 36]
    uint32_t* v_u = (uint32_t*)(sm + VS_OFF);   // [dv=128][m 212]
    float*    b_s = sm + BS_OFF;                // [196]

    const int bh = blockIdx.x, b = bh >> 3, h = bh & 7;
    const int tid = threadIdx.x;
    const size_t gbase = (size_t)b * NSP;

    // ---- zero padding regions ----
    for (int i = tid; i < 32 * 20; i += ATTN_THREADS) {          // q cols 196..215
        q_u[(i / 20) * QPITCH + 196 + (i % 20)] = 0u;
    }
    for (int i = tid; i < 12 * KPITCH; i += ATTN_THREADS) {      // k rows 196..207
        k_u[(196 + i / KPITCH) * KPITCH + (i % KPITCH)] = 0u;
    }
    for (int i = tid; i < 128 * 16; i += ATTN_THREADS) {         // v cols 196..211
        v_u[(i / 16) * VPITCH + 196 + (i % 16)] = 0u;
    }
    // ---- loads (convert to tf32 bit patterns) ----
    for (int i = tid; i < 32 * 196; i += ATTN_THREADS) {
        int d = i / 196, n = i % 196;
        q_u[d * QPITCH + n] = f2tf32(qbuf[(size_t)(h * 32 + d) * NTOT + gbase + n]);
    }
    for (int i = tid; i < 32 * 196; i += ATTN_THREADS) {
        int d = i / 196, m = i % 196;
        k_u[m * KPITCH + d] = f2tf32(qkv[(size_t)(NH_KD + h * 32 + d) * NTOT + gbase + m]);
    }
    for (int i = tid; i < 128 * 196; i += ATTN_THREADS) {
        int d = i / 196, m = i % 196;
        v_u[d * VPITCH + m] = f2tf32(qkv[(size_t)(2 * NH_KD + h * 128 + d) * NTOT + gbase + m]);
    }
    for (int i = tid; i < 196; i += ATTN_THREADS) b_s[i] = biases[h * NSP + i];
    __syncthreads();

    const int warp = tid >> 5, lane = tid & 31, grp = lane >> 2, tig = lane & 3;
    const float scale = 0.17677669529663687f;  // 1/sqrt(32)

    for (int s = warp; s < 26; s += 13) {
        const int q0 = s * 8;

        // ---- S^T = K^T x Q : 13 key m-tiles x (8 queries) ----
        float sc[13][4];
#pragma unroll
        for (int T = 0; T < 13; T++) { sc[T][0]=sc[T][1]=sc[T][2]=sc[T][3]=0.f; }

#pragma unroll
        for (int kst = 0; kst < 4; kst++) {
            const int kb = kst * 8;
            uint32_t bf0 = q_u[(kb + tig    ) * QPITCH + q0 + grp];
            uint32_t bf1 = q_u[(kb + tig + 4) * QPITCH + q0 + grp];
#pragma unroll
            for (int T = 0; T < 13; T++) {
                uint32_t a0 = k_u[(T * 16 + grp    ) * KPITCH + kb + tig];
                uint32_t a1 = k_u[(T * 16 + grp + 8) * KPITCH + kb + tig];
                uint32_t a2 = k_u[(T * 16 + grp    ) * KPITCH + kb + tig + 4];
                uint32_t a3 = k_u[(T * 16 + grp + 8) * KPITCH + kb + tig + 4];
                MMA_TF32(sc[T], a0, a1, a2, a3, bf0, bf1);
            }
        }

        // ---- scale + bias + mask; row max over keys ----
        const int qa = q0 + 2 * tig, qb = qa + 1;
        const bool qv = qa < 196;            // qa even -> pair valid together
        const int qaC = qv ? qa : 0;
        const int qbC = qv ? qb : 0;
        float mx0 = -1e30f, mx1 = -1e30f;
#pragma unroll
        for (int T = 0; T < 13; T++) {
            int k0 = T * 16 + grp, k1 = k0 + 8;
            int k0C = (k0 < 196) ? k0 : 0;
            int k1C = (k1 < 196) ? k1 : 0;
            float b00 = b_s[__ldg(&idxs[qaC * NSP + k0C])];
            float b01 = b_s[__ldg(&idxs[qbC * NSP + k0C])];
            float b10 = b_s[__ldg(&idxs[qaC * NSP + k1C])];
            float b11 = b_s[__ldg(&idxs[qbC * NSP + k1C])];
            sc[T][0] = (k0 < 196 && qv) ? sc[T][0] * scale + b00 : -1e30f;
            sc[T][1] = (k0 < 196 && qv) ? sc[T][1] * scale + b01 : -1e30f;
            sc[T][2] = (k1 < 196 && qv) ? sc[T][2] * scale + b10 : -1e30f;
            sc[T][3] = (k1 < 196 && qv) ? sc[T][3] * scale + b11 : -1e30f;
            mx0 = fmaxf(mx0, fmaxf(sc[T][0], sc[T][2]));
            mx1 = fmaxf(mx1, fmaxf(sc[T][1], sc[T][3]));
        }
#pragma unroll
        for (int off = 4; off <= 16; off <<= 1) {
            mx0 = fmaxf(mx0, __shfl_xor_sync(0xFFFFFFFFu, mx0, off));
            mx1 = fmaxf(mx1, __shfl_xor_sync(0xFFFFFFFFu, mx1, off));
        }
        // ---- exp + row sum ----
        float sum0 = 0.f, sum1 = 0.f;
#pragma unroll
        for (int T = 0; T < 13; T++) {
            sc[T][0] = __expf(sc[T][0] - mx0); sum0 += sc[T][0];
            sc[T][1] = __expf(sc[T][1] - mx1); sum1 += sc[T][1];
            sc[T][2] = __expf(sc[T][2] - mx0); sum0 += sc[T][2];
            sc[T][3] = __expf(sc[T][3] - mx1); sum1 += sc[T][3];
        }
#pragma unroll
        for (int off = 4; off <= 16; off <<= 1) {
            sum0 += __shfl_xor_sync(0xFFFFFFFFu, sum0, off);
            sum1 += __shfl_xor_sync(0xFFFFFFFFu, sum1, off);
        }

        // ---- O^T = V x P^T ; P^T operand from S accumulators via shuffles ----
        float o[8][4];
#pragma unroll
        for (int dt = 0; dt < 8; dt++) { o[dt][0]=o[dt][1]=o[dt][2]=o[dt][3]=0.f; }

        const int srcA = tig * 4 + (grp >> 1);
#pragma unroll
        for (int kb = 0; kb < 26; kb++) {
            const int T = kb >> 1;
            float e0 = (kb & 1) ? sc[T][2] : sc[T][0];
            float e1 = (kb & 1) ? sc[T][3] : sc[T][1];
            float x0 = __shfl_sync(0xFFFFFFFFu, e0, srcA);
            float x1 = __shfl_sync(0xFFFFFFFFu, e1, srcA);
            float y0 = __shfl_sync(0xFFFFFFFFu, e0, srcA + 16);
            float y1 = __shfl_sync(0xFFFFFFFFu, e1, srcA + 16);
            uint32_t pb0 = f2tf32((grp & 1) ? x1 : x0);
            uint32_t pb1 = f2tf32((grp & 1) ? y1 : y0);
            const int m0 = kb * 8;
#pragma unroll
            for (int dt = 0; dt < 8; dt++) {
                uint32_t a0 = v_u[(dt * 16 + grp    ) * VPITCH + m0 + tig];
                uint32_t a1 = v_u[(dt * 16 + grp + 8) * VPITCH + m0 + tig];
                uint32_t a2 = v_u[(dt * 16 + grp    ) * VPITCH + m0 + tig + 4];
                uint32_t a3 = v_u[(dt * 16 + grp + 8) * VPITCH + m0 + tig + 4];
                MMA_TF32(o[dt], a0, a1, a2, a3, pb0, pb1);
            }
        }

        // ---- normalize + ReLU + store ----
        if (qv) {
            float inv0 = 1.f / sum0, inv1 = 1.f / sum1;
            size_t obase = (size_t)(h * DV) * NTOT + gbase + qa;
#pragma unroll
            for (int dt = 0; dt < 8; dt++) {
                float2 p0 = make_float2(fmaxf(o[dt][0] * inv0, 0.f),
                                        fmaxf(o[dt][1] * inv1, 0.f));
                float2 p1 = make_float2(fmaxf(o[dt][2] * inv0, 0.f),
                                        fmaxf(o[dt][3] * inv1, 0.f));
                *(float2*)&obuf[obase + (size_t)(dt * 16 + grp    ) * NTOT] = p0;
                *(float2*)&obuf[obase + (size_t)(dt * 16 + grp + 8) * NTOT] = p1;
            }
        }
    }
}

// ---------------------------------------------------------------------------
// launch
// ---------------------------------------------------------------------------
extern "C" void kernel_launch(void* const* d_in, const int* in_sizes, int n_in,
                              void* d_out, int out_size)
{
    const float* x      = (const float*)d_in[0];
    const float* qkv_w  = (const float*)d_in[1];
    const float* qkv_g  = (const float*)d_in[2];
    const float* qkv_b  = (const float*)d_in[3];
    const float* qkv_m  = (const float*)d_in[4];
    const float* qkv_v  = (const float*)d_in[5];
    const float* dw_w   = (const float*)d_in[6];
    const float* dw_g   = (const float*)d_in[7];
    const float* dw_b   = (const float*)d_in[8];
    const float* dw_m   = (const float*)d_in[9];
    const float* dw_v   = (const float*)d_in[10];
    const float* proj_w = (const float*)d_in[11];
    const float* proj_g = (const float*)d_in[12];
    const float* proj_b = (const float*)d_in[13];
    const float* proj_m = (const float*)d_in[14];
    const float* proj_v = (const float*)d_in[15];
    const float* ab     = (const float*)d_in[16];
    const int*   idxs   = (const int*)  d_in[17];
    float* out = (float*)d_out;

    float *xT, *qkvb, *qb, *ob;
    cudaGetSymbolAddress((void**)&xT,   g_xT);
    cudaGetSymbolAddress((void**)&qkvb, g_qkv);
    cudaGetSymbolAddress((void**)&qb,   g_q);
    cudaGetSymbolAddress((void**)&ob,   g_o);

    cudaFuncSetAttribute(k_attn, cudaFuncAttributeMaxDynamicSharedMemorySize, ATTN_SMEM);

    // K0: transpose
    k_transpose<<<(DIM * NTOT + 255) / 256, 256>>>(x, xT);

    // K1: qkv GEMM + BN  (M=1536, N=50176, K=384)
    {
        dim3 grid(H_QKV / GBM, NTOT / GBN);
        k_gemm_tf32<<<grid, 256>>>(qkv_w, xT, qkvb, H_QKV, NTOT, DIM,
                                   qkv_g, qkv_b, qkv_m, qkv_v, 0);
    }

    // K2: depthwise conv + BN
    k_dwconv_bn<<<(NH_KD * NTOT + 255) / 256, 256>>>(qkvb, dw_w, qb,
                                                     dw_g, dw_b, dw_m, dw_v);

    // K3: attention (+ ReLU), tensor-core version
    k_attn<<<BATCH * HEADS, ATTN_THREADS, ATTN_SMEM>>>(qb, qkvb, ab, idxs, ob);

    // K4: proj GEMM + BN, scatter-store into [B, 384, 14, 14]
    {
        dim3 grid(DIM / GBM, NTOT / GBN);
        k_gemm_tf32<<<grid, 256>>>(proj_w, ob, out, DIM, NTOT, DH,
                                   proj_g, proj_b, proj_m, proj_v, 1);
    }
}

// round 4
// speedup vs baseline: 1.9964x; 1.9964x over previous
#include <cuda_runtime.h>
#include <math.h>
#include <stdint.h>

// ---------------------------------------------------------------------------
// Problem constants
// ---------------------------------------------------------------------------
#define BATCH   256
#define DIM     384
#define KEY_DIM 32
#define HEADS   8
#define RES     14
#define NSP     196
#define NH_KD   256
#define DV      128
#define DH      1024
#define H_QKV   1536
#define NTOT    (BATCH*NSP)    // 50176
#define EPS     1e-5f

// ---------------------------------------------------------------------------
// Scratch
// ---------------------------------------------------------------------------
__device__ float g_xT [DIM   * NTOT];
__device__ float g_qkv[H_QKV * NTOT];
__device__ float g_q  [NH_KD * NTOT];
__device__ float g_o  [DH    * NTOT];

// mma on raw fp32 bit patterns (HW truncates to tf32)
#define MMA_TF32(D, A0, A1, A2, A3, B0, B1)                                    \
    asm volatile(                                                              \
        "mma.sync.aligned.m16n8k8.row.col.f32.tf32.tf32.f32 "                  \
        "{%0,%1,%2,%3}, {%4,%5,%6,%7}, {%8,%9}, {%0,%1,%2,%3};"                \
        : "+f"(D[0]), "+f"(D[1]), "+f"(D[2]), "+f"(D[3])                       \
        : "r"(A0), "r"(A1), "r"(A2), "r"(A3), "r"(B0), "r"(B1))

#define CPASYNC16(dst_smem, src_gmem)                                          \
    asm volatile("cp.async.cg.shared.global [%0], [%1], 16;"                   \
                 :: "r"(dst_smem), "l"(src_gmem))

// ---------------------------------------------------------------------------
// K0: transpose x [B,384,196] -> xT [384, B*196]
// ---------------------------------------------------------------------------
__global__ void k_transpose(const float* __restrict__ x, float* __restrict__ xT) {
    int i = blockIdx.x * 256 + threadIdx.x;
    if (i >= DIM * NTOT) return;
    int n = i % NSP;
    int c = (i / NSP) % DIM;
    int b = i / (NSP * DIM);
    xT[c * NTOT + b * NSP + n] = x[i];
}

// ---------------------------------------------------------------------------
// TF32 GEMM, cp.async double-buffered, fused BN epilogue.
//   C[M,N] = BN( A[M,K] * B[K,N] );  block 128x128, BK=32, 8 warps.
// ---------------------------------------------------------------------------
#define GBM 128
#define GBN 128
#define GBK 32

__global__ __launch_bounds__(256, 2) void k_gemm_tf32(
    const float* __restrict__ A, const float* __restrict__ B,
    float* __restrict__ C, int M, int N, int K,
    const float* __restrict__ gg, const float* __restrict__ bb,
    const float* __restrict__ mm, const float* __restrict__ vv,
    int scatter)
{
    __shared__ float As[2][GBM][GBK + 4];   // pitch 36 words
    __shared__ float Bs[2][GBK][GBN + 8];   // pitch 136 words

    const int tid  = threadIdx.x;
    const int lane = tid & 31;
    const int wid  = tid >> 5;
    const int wm   = wid & 1;
    const int wn   = wid >> 1;
    const int row0 = blockIdx.x * GBM;
    const int col0 = blockIdx.y * GBN;
    const int grp  = lane >> 2;
    const int tig  = lane & 3;

    // per-thread load coordinates
    const int ar = tid >> 3, akq = (tid & 7) * 4;      // A: 2 rows strided 32? no: 4 chunks
    const int bkr = tid >> 5, bnq = (tid & 31) * 4;

    float acc[4][4][4];
#pragma unroll
    for (int a = 0; a < 4; a++)
#pragma unroll
        for (int b = 0; b < 4; b++)
#pragma unroll
            for (int c = 0; c < 4; c++) acc[a][b][c] = 0.f;

    const int nk = K / GBK;

#define LOAD_TILE(k0, buf)                                                       \
    {                                                                            \
        _Pragma("unroll")                                                        \
        for (int i = 0; i < 4; i++) {                                            \
            int r = ar + i * 32;                                                 \
            const float* src = &A[(size_t)(row0 + r) * K + (k0) + akq];          \
            uint32_t dst = (uint32_t)__cvta_generic_to_shared(&As[buf][r][akq]); \
            CPASYNC16(dst, src);                                                 \
        }                                                                        \
        _Pragma("unroll")                                                        \
        for (int i = 0; i < 4; i++) {                                            \
            int kr = bkr + i * 8;                                                \
            const float* src = &B[(size_t)((k0) + kr) * N + col0 + bnq];         \
            uint32_t dst = (uint32_t)__cvta_generic_to_shared(&Bs[buf][kr][bnq]);\
            CPASYNC16(dst, src);                                                 \
        }                                                                        \
        asm volatile("cp.async.commit_group;");                                  \
    }

    LOAD_TILE(0, 0)

    for (int it = 0; it < nk; it++) {
        asm volatile("cp.async.wait_group 0;");
        __syncthreads();
        if (it + 1 < nk) LOAD_TILE((it + 1) * GBK, (it + 1) & 1)
        const int buf = it & 1;

#pragma unroll
        for (int ks = 0; ks < 4; ks++) {
            const int kb = ks * 8;
            uint32_t af[4][4], bf[4][2];
#pragma unroll
            for (int mf = 0; mf < 4; mf++) {
                int r = wm * 64 + mf * 16 + grp;
                af[mf][0] = __float_as_uint(As[buf][r    ][kb + tig]);
                af[mf][1] = __float_as_uint(As[buf][r + 8][kb + tig]);
                af[mf][2] = __float_as_uint(As[buf][r    ][kb + tig + 4]);
                af[mf][3] = __float_as_uint(As[buf][r + 8][kb + tig + 4]);
            }
#pragma unroll
            for (int nf = 0; nf < 4; nf++) {
                int c = wn * 32 + nf * 8 + grp;
                bf[nf][0] = __float_as_uint(Bs[buf][kb + tig    ][c]);
                bf[nf][1] = __float_as_uint(Bs[buf][kb + tig + 4][c]);
            }
#pragma unroll
            for (int mf = 0; mf < 4; mf++)
#pragma unroll
                for (int nf = 0; nf < 4; nf++)
                    MMA_TF32(acc[mf][nf], af[mf][0], af[mf][1], af[mf][2], af[mf][3],
                             bf[nf][0], bf[nf][1]);
        }
        __syncthreads();
    }

#pragma unroll
    for (int mf = 0; mf < 4; mf++) {
        int r0 = row0 + wm * 64 + mf * 16 + grp;
        int r1 = r0 + 8;
        float s0 = gg[r0] * rsqrtf(vv[r0] + EPS);
        float h0 = bb[r0] - mm[r0] * s0;
        float s1 = gg[r1] * rsqrtf(vv[r1] + EPS);
        float h1 = bb[r1] - mm[r1] * s1;
#pragma unroll
        for (int nf = 0; nf < 4; nf++) {
            int cc = col0 + wn * 32 + nf * 8 + tig * 2;
            float v00 = acc[mf][nf][0] * s0 + h0;
            float v01 = acc[mf][nf][1] * s0 + h0;
            float v10 = acc[mf][nf][2] * s1 + h1;
            float v11 = acc[mf][nf][3] * s1 + h1;
            if (scatter == 0) {
                *(float2*)&C[(size_t)r0 * N + cc] = make_float2(v00, v01);
                *(float2*)&C[(size_t)r1 * N + cc] = make_float2(v10, v11);
            } else {
                int b0i = cc / NSP,      sp0 = cc - b0i * NSP;
                int b1i = (cc+1) / NSP,  sp1 = (cc+1) - b1i * NSP;
                C[b0i * (DIM * NSP) + r0 * NSP + sp0] = v00;
                C[b1i * (DIM * NSP) + r0 * NSP + sp1] = v01;
                C[b0i * (DIM * NSP) + r1 * NSP + sp0] = v10;
                C[b1i * (DIM * NSP) + r1 * NSP + sp1] = v11;
            }
        }
    }
}

// ---------------------------------------------------------------------------
// K2: depthwise 3x3 conv + BN
// ---------------------------------------------------------------------------
__global__ void k_dwconv_bn(const float* __restrict__ qkv,
                            const float* __restrict__ w,
                            float* __restrict__ qout,
                            const float* __restrict__ gg, const float* __restrict__ bb,
                            const float* __restrict__ mm, const float* __restrict__ vv)
{
    int i = blockIdx.x * 256 + threadIdx.x;
    if (i >= NH_KD * NTOT) return;
    int sp = i % NSP;
    int b  = (i / NSP) % BATCH;
    int c  = i / NTOT;
    int y = sp / RES, x = sp % RES;

    const float* base = qkv + c * NTOT + b * NSP;
    const float* wc = w + c * 9;
    float acc = 0.f;
#pragma unroll
    for (int dy = -1; dy <= 1; dy++) {
        int yy = y + dy;
        if (yy < 0 || yy >= RES) continue;
#pragma unroll
        for (int dx = -1; dx <= 1; dx++) {
            int xx = x + dx;
            if (xx < 0 || xx >= RES) continue;
            acc = fmaf(wc[(dy + 1) * 3 + (dx + 1)], base[yy * RES + xx], acc);
        }
    }
    float s  = gg[c] * rsqrtf(vv[c] + EPS);
    float sh = bb[c] - mm[c] * s;
    qout[i] = acc * s + sh;
}

// ---------------------------------------------------------------------------
// K3: tensor-core attention, 2 CTAs per (b,h) (each owns 64 of 128 dv rows).
//   256 threads = 8 warps; each warp handles query stripes s, s+8, ...
//   smem ~110 KB -> 2 CTAs/SM.  Raw fp32 bits into tf32 mma (no cvt).
// ---------------------------------------------------------------------------
#define ATTN_THREADS 256
#define VROWS 64
#define QPITCH 216   // %32=24 -> B-frag loads conflict-free
#define KPITCH 36    // %32=4
#define VPITCH 212   // %32=20
#define QS_OFF 0
#define KS_OFF (32*QPITCH)               // 6912
#define VS_OFF (KS_OFF + 208*KPITCH)     // 14400
#define BS_OFF (VS_OFF + VROWS*VPITCH)   // 27968
#define ATTN_SMEM ((BS_OFF + 200)*4)     // 112,672 B

__global__ __launch_bounds__(ATTN_THREADS, 2) void k_attn(
    const float* __restrict__ qbuf, const float* __restrict__ qkv,
    const float* __restrict__ biases, const int* __restrict__ idxs,
    float* __restrict__ obuf)
{
    extern __shared__ float sm[];
    float* q_s = sm + QS_OFF;   // [d=32][q 216]
    float* k_s = sm + KS_OFF;   // [m=208][d 36]
    float* v_s = sm + VS_OFF;   // [dv=64][m 212]
    float* b_s = sm + BS_OFF;   // [196]

    const int half = blockIdx.x & 1;
    const int bh   = blockIdx.x >> 1;
    const int b = bh >> 3, h = bh & 7;
    const int tid = threadIdx.x;
    const size_t gbase = (size_t)b * NSP;

    // zero pads
    for (int i = tid; i < 32 * 20; i += ATTN_THREADS)
        q_s[(i / 20) * QPITCH + 196 + (i % 20)] = 0.f;
    for (int i = tid; i < 12 * KPITCH; i += ATTN_THREADS)
        k_s[(196 + i / KPITCH) * KPITCH + (i % KPITCH)] = 0.f;
    for (int i = tid; i < VROWS * 16; i += ATTN_THREADS)
        v_s[(i / 16) * VPITCH + 196 + (i % 16)] = 0.f;
    // loads
    for (int i = tid; i < 32 * 196; i += ATTN_THREADS) {
        int d = i / 196, n = i % 196;
        q_s[d * QPITCH + n] = qbuf[(size_t)(h * 32 + d) * NTOT + gbase + n];
    }
    for (int i = tid; i < 32 * 196; i += ATTN_THREADS) {
        int d = i / 196, m = i % 196;
        k_s[m * KPITCH + d] = qkv[(size_t)(NH_KD + h * 32 + d) * NTOT + gbase + m];
    }
    for (int i = tid; i < VROWS * 196; i += ATTN_THREADS) {
        int d = i / 196, m = i % 196;
        v_s[d * VPITCH + m] =
            qkv[(size_t)(2 * NH_KD + h * 128 + half * VROWS + d) * NTOT + gbase + m];
    }
    for (int i = tid; i < 196; i += ATTN_THREADS) b_s[i] = biases[h * NSP + i];
    __syncthreads();

    const int warp = tid >> 5, lane = tid & 31, grp = lane >> 2, tig = lane & 3;
    const float scale = 0.17677669529663687f;

    for (int s = warp; s < 26; s += 8) {
        const int q0 = s * 8;

        // ---- S^T = K^T x Q ----
        float sc[13][4];
#pragma unroll
        for (int T = 0; T < 13; T++) { sc[T][0]=sc[T][1]=sc[T][2]=sc[T][3]=0.f; }

#pragma unroll
        for (int kst = 0; kst < 4; kst++) {
            const int kb = kst * 8;
            uint32_t bf0 = __float_as_uint(q_s[(kb + tig    ) * QPITCH + q0 + grp]);
            uint32_t bf1 = __float_as_uint(q_s[(kb + tig + 4) * QPITCH + q0 + grp]);
#pragma unroll
            for (int T = 0; T < 13; T++) {
                uint32_t a0 = __float_as_uint(k_s[(T * 16 + grp    ) * KPITCH + kb + tig]);
                uint32_t a1 = __float_as_uint(k_s[(T * 16 + grp + 8) * KPITCH + kb + tig]);
                uint32_t a2 = __float_as_uint(k_s[(T * 16 + grp    ) * KPITCH + kb + tig + 4]);
                uint32_t a3 = __float_as_uint(k_s[(T * 16 + grp + 8) * KPITCH + kb + tig + 4]);
                MMA_TF32(sc[T], a0, a1, a2, a3, bf0, bf1);
            }
        }

        // ---- scale + bias + mask; max ----
        const int qa = q0 + 2 * tig, qb = qa + 1;
        const bool qv = qa < 196;
        const int qaC = qv ? qa : 0;
        const int qbC = qv ? qb : 0;
        float mx0 = -1e30f, mx1 = -1e30f;
#pragma unroll
        for (int T = 0; T < 13; T++) {
            int k0 = T * 16 + grp, k1 = k0 + 8;
            int k0C = (k0 < 196) ? k0 : 0;
            int k1C = (k1 < 196) ? k1 : 0;
            float b00 = b_s[__ldg(&idxs[qaC * NSP + k0C])];
            float b01 = b_s[__ldg(&idxs[qbC * NSP + k0C])];
            float b10 = b_s[__ldg(&idxs[qaC * NSP + k1C])];
            float b11 = b_s[__ldg(&idxs[qbC * NSP + k1C])];
            sc[T][0] = (k0 < 196 && qv) ? sc[T][0] * scale + b00 : -1e30f;
            sc[T][1] = (k0 < 196 && qv) ? sc[T][1] * scale + b01 : -1e30f;
            sc[T][2] = (k1 < 196 && qv) ? sc[T][2] * scale + b10 : -1e30f;
            sc[T][3] = (k1 < 196 && qv) ? sc[T][3] * scale + b11 : -1e30f;
            mx0 = fmaxf(mx0, fmaxf(sc[T][0], sc[T][2]));
            mx1 = fmaxf(mx1, fmaxf(sc[T][1], sc[T][3]));
        }
#pragma unroll
        for (int off = 4; off <= 16; off <<= 1) {
            mx0 = fmaxf(mx0, __shfl_xor_sync(0xFFFFFFFFu, mx0, off));
            mx1 = fmaxf(mx1, __shfl_xor_sync(0xFFFFFFFFu, mx1, off));
        }
        float sum0 = 0.f, sum1 = 0.f;
#pragma unroll
        for (int T = 0; T < 13; T++) {
            sc[T][0] = __expf(sc[T][0] - mx0); sum0 += sc[T][0];
            sc[T][1] = __expf(sc[T][1] - mx1); sum1 += sc[T][1];
            sc[T][2] = __expf(sc[T][2] - mx0); sum0 += sc[T][2];
            sc[T][3] = __expf(sc[T][3] - mx1); sum1 += sc[T][3];
        }
#pragma unroll
        for (int off = 4; off <= 16; off <<= 1) {
            sum0 += __shfl_xor_sync(0xFFFFFFFFu, sum0, off);
            sum1 += __shfl_xor_sync(0xFFFFFFFFu, sum1, off);
        }

        // ---- O^T = V x P^T (P^T frags from S accumulators via shuffles) ----
        float o[4][4];
#pragma unroll
        for (int dt = 0; dt < 4; dt++) { o[dt][0]=o[dt][1]=o[dt][2]=o[dt][3]=0.f; }

        const int srcA = tig * 4 + (grp >> 1);
#pragma unroll
        for (int kb = 0; kb < 26; kb++) {
            const int T = kb >> 1;
            float e0 = (kb & 1) ? sc[T][2] : sc[T][0];
            float e1 = (kb & 1) ? sc[T][3] : sc[T][1];
            float x0 = __shfl_sync(0xFFFFFFFFu, e0, srcA);
            float x1 = __shfl_sync(0xFFFFFFFFu, e1, srcA);
            float y0 = __shfl_sync(0xFFFFFFFFu, e0, srcA + 16);
            float y1 = __shfl_sync(0xFFFFFFFFu, e1, srcA + 16);
            uint32_t pb0 = __float_as_uint((grp & 1) ? x1 : x0);
            uint32_t pb1 = __float_as_uint((grp & 1) ? y1 : y0);
            const int m0 = kb * 8;
#pragma unroll
            for (int dt = 0; dt < 4; dt++) {
                uint32_t a0 = __float_as_uint(v_s[(dt * 16 + grp    ) * VPITCH + m0 + tig]);
                uint32_t a1 = __float_as_uint(v_s[(dt * 16 + grp + 8) * VPITCH + m0 + tig]);
                uint32_t a2 = __float_as_uint(v_s[(dt * 16 + grp    ) * VPITCH + m0 + tig + 4]);
                uint32_t a3 = __float_as_uint(v_s[(dt * 16 + grp + 8) * VPITCH + m0 + tig + 4]);
                MMA_TF32(o[dt], a0, a1, a2, a3, pb0, pb1);
            }
        }

        // ---- normalize + ReLU + store ----
        if (qv) {
            float inv0 = 1.f / sum0, inv1 = 1.f / sum1;
            size_t obase = (size_t)(h * DV + half * VROWS) * NTOT + gbase + qa;
#pragma unroll
            for (int dt = 0; dt < 4; dt++) {
                float2 p0 = make_float2(fmaxf(o[dt][0] * inv0, 0.f),
                                        fmaxf(o[dt][1] * inv1, 0.f));
                float2 p1 = make_float2(fmaxf(o[dt][2] * inv0, 0.f),
                                        fmaxf(o[dt][3] * inv1, 0.f));
                *(float2*)&obuf[obase + (size_t)(dt * 16 + grp    ) * NTOT] = p0;
                *(float2*)&obuf[obase + (size_t)(dt * 16 + grp + 8) * NTOT] = p1;
            }
        }
    }
}

// ---------------------------------------------------------------------------
// launch
// ---------------------------------------------------------------------------
extern "C" void kernel_launch(void* const* d_in, const int* in_sizes, int n_in,
                              void* d_out, int out_size)
{
    const float* x      = (const float*)d_in[0];
    const float* qkv_w  = (const float*)d_in[1];
    const float* qkv_g  = (const float*)d_in[2];
    const float* qkv_b  = (const float*)d_in[3];
    const float* qkv_m  = (const float*)d_in[4];
    const float* qkv_v  = (const float*)d_in[5];
    const float* dw_w   = (const float*)d_in[6];
    const float* dw_g   = (const float*)d_in[7];
    const float* dw_b   = (const float*)d_in[8];
    const float* dw_m   = (const float*)d_in[9];
    const float* dw_v   = (const float*)d_in[10];
    const float* proj_w = (const float*)d_in[11];
    const float* proj_g = (const float*)d_in[12];
    const float* proj_b = (const float*)d_in[13];
    const float* proj_m = (const float*)d_in[14];
    const float* proj_v = (const float*)d_in[15];
    const float* ab     = (const float*)d_in[16];
    const int*   idxs   = (const int*)  d_in[17];
    float* out = (float*)d_out;

    float *xT, *qkvb, *qb, *ob;
    cudaGetSymbolAddress((void**)&xT,   g_xT);
    cudaGetSymbolAddress((void**)&qkvb, g_qkv);
    cudaGetSymbolAddress((void**)&qb,   g_q);
    cudaGetSymbolAddress((void**)&ob,   g_o);

    cudaFuncSetAttribute(k_attn, cudaFuncAttributeMaxDynamicSharedMemorySize, ATTN_SMEM);

    k_transpose<<<(DIM * NTOT + 255) / 256, 256>>>(x, xT);

    {
        dim3 grid(H_QKV / GBM, NTOT / GBN);
        k_gemm_tf32<<<grid, 256>>>(qkv_w, xT, qkvb, H_QKV, NTOT, DIM,
                                   qkv_g, qkv_b, qkv_m, qkv_v, 0);
    }

    k_dwconv_bn<<<(NH_KD * NTOT + 255) / 256, 256>>>(qkvb, dw_w, qb,
                                                     dw_g, dw_b, dw_m, dw_v);

    k_attn<<<BATCH * HEADS * 2, ATTN_THREADS, ATTN_SMEM>>>(qb, qkvb, ab, idxs, ob);

    {
        dim3 grid(DIM / GBM, NTOT / GBN);
        k_gemm_tf32<<<grid, 256>>>(proj_w, ob, out, DIM, NTOT, DH,
                                   proj_g, proj_b, proj_m, proj_v, 1);
    }
}

// round 6
// speedup vs baseline: 3.3211x; 1.6636x over previous
#include <cuda_runtime.h>
#include <cuda_fp16.h>
#include <math.h>
#include <stdint.h>

// ---------------------------------------------------------------------------
// Problem constants
// ---------------------------------------------------------------------------
#define BATCH   256
#define DIM     384
#define KEY_DIM 32
#define HEADS   8
#define RES     14
#define NSP     196
#define NH_KD   256
#define DV      128
#define DH      1024
#define H_QKV   1536
#define NTOT    (BATCH*NSP)    // 50176
#define EPS     1e-5f

// ---------------------------------------------------------------------------
// Scratch (device globals)
// ---------------------------------------------------------------------------
__device__ __half g_xT [DIM   * NTOT];
__device__ __half g_qkv[H_QKV * NTOT];
__device__ __half g_q  [NH_KD * NTOT];
__device__ __half g_o  [DH    * NTOT];
__device__ __half g_wq [H_QKV * DIM];
__device__ __half g_wp [DIM   * DH];

// ---------------------------------------------------------------------------
// PTX helpers
// ---------------------------------------------------------------------------
#define MMA_F16(D, A0, A1, A2, A3, B0, B1)                                     \
    asm volatile(                                                              \
        "mma.sync.aligned.m16n8k16.row.col.f32.f16.f16.f32 "                   \
        "{%0,%1,%2,%3}, {%4,%5,%6,%7}, {%8,%9}, {%0,%1,%2,%3};"                \
        : "+f"(D[0]), "+f"(D[1]), "+f"(D[2]), "+f"(D[3])                       \
        : "r"(A0), "r"(A1), "r"(A2), "r"(A3), "r"(B0), "r"(B1))

#define LDSM4(R0, R1, R2, R3, addr)                                            \
    asm volatile("ldmatrix.sync.aligned.m8n8.x4.shared.b16 {%0,%1,%2,%3}, [%4];" \
        : "=r"(R0), "=r"(R1), "=r"(R2), "=r"(R3) : "r"(addr))

#define LDSM4T(R0, R1, R2, R3, addr)                                           \
    asm volatile("ldmatrix.sync.aligned.m8n8.x4.trans.shared.b16 {%0,%1,%2,%3}, [%4];" \
        : "=r"(R0), "=r"(R1), "=r"(R2), "=r"(R3) : "r"(addr))

#define LDSM2T(R0, R1, addr)                                                   \
    asm volatile("ldmatrix.sync.aligned.m8n8.x2.trans.shared.b16 {%0,%1}, [%2];" \
        : "=r"(R0), "=r"(R1) : "r"(addr))

#define CPASYNC16(dst_smem, src_gmem)                                          \
    asm volatile("cp.async.cg.shared.global [%0], [%1], 16;"                   \
                 :: "r"(dst_smem), "l"(src_gmem))

__device__ __forceinline__ uint32_t packh2(float a, float b) {
    __half2 h = __floats2half2_rn(a, b);
    return *reinterpret_cast<uint32_t*>(&h);
}

// ---------------------------------------------------------------------------
// K_pre: fp32 -> fp16 weight conversion
// ---------------------------------------------------------------------------
__global__ void k_f2h(const float* __restrict__ a, __half* __restrict__ o, int n) {
    int i = blockIdx.x * 256 + threadIdx.x;
    if (i < n) o[i] = __float2half(a[i]);
}

// ---------------------------------------------------------------------------
// K0: transpose x [B,384,196] -> xT [384, B*196] (half)
// ---------------------------------------------------------------------------
__global__ void k_transpose(const float* __restrict__ x, __half* __restrict__ xT) {
    int i = blockIdx.x * 256 + threadIdx.x;
    if (i >= DIM * NTOT) return;
    int n = i % NSP;
    int c = (i / NSP) % DIM;
    int b = i / (NSP * DIM);
    xT[c * NTOT + b * NSP + n] = __float2half(x[i]);
}

// ---------------------------------------------------------------------------
// FP16 GEMM, cp.async double-buffered, ldmatrix fragments, fused BN epilogue.
//   C[M,N] = BN( A[M,K] * B[K,N] );  block 128x128, BK=32, 8 warps.
//   scatter==0 -> Ch (half, row-major); scatter==1 -> Cf (f32, [B,384,14,14])
// ---------------------------------------------------------------------------
#define GBM 128
#define GBN 128
#define GBK 32
#define AS_BUF_BYTES (GBM*40*2)    // 10240
#define BS_BUF_BYTES (GBK*136*2)   //  8704

__global__ __launch_bounds__(256, 2) void k_gemm_f16(
    const __half* __restrict__ A, const __half* __restrict__ B,
    __half* __restrict__ Ch, float* __restrict__ Cf,
    int M, int N, int K,
    const float* __restrict__ gg, const float* __restrict__ bb,
    const float* __restrict__ mm, const float* __restrict__ vv,
    int scatter)
{
    __shared__ __half As[2][GBM][40];    // [m][k] pitch 40 halfs (80 B)
    __shared__ __half Bs[2][GBK][136];   // [k][n] pitch 136 halfs (272 B)

    const int tid  = threadIdx.x;
    const int lane = tid & 31;
    const int wid  = tid >> 5;
    const int wm   = wid & 1;
    const int wn   = wid >> 1;
    const int row0 = blockIdx.x * GBM;
    const int col0 = blockIdx.y * GBN;
    const int grp  = lane >> 2;
    const int tig  = lane & 3;

    const uint32_t as0 = (uint32_t)__cvta_generic_to_shared(&As[0][0][0]);
    const uint32_t bs0 = (uint32_t)__cvta_generic_to_shared(&Bs[0][0][0]);

    // fragment smem byte offsets (within buffer)
    uint32_t offA[4];
#pragma unroll
    for (int mf = 0; mf < 4; mf++) {
        int r = wm * 64 + mf * 16 + (lane & 15);
        offA[mf] = (uint32_t)(r * 40 + ((lane & 16) ? 8 : 0)) * 2;
    }
    const int rB = (lane & 7) + ((lane & 8) ? 8 : 0);
    const uint32_t offB0 = (uint32_t)(rB * 136 + wn * 32 + ((lane & 16) ? 8 : 0)) * 2;
    const uint32_t offB1 = offB0 + 32;   // +16 cols

    float acc[4][4][4];
#pragma unroll
    for (int a = 0; a < 4; a++)
#pragma unroll
        for (int b = 0; b < 4; b++)
#pragma unroll
            for (int c = 0; c < 4; c++) acc[a][b][c] = 0.f;

#define LOAD_TILE(k0, buf)                                                        \
    {                                                                             \
        _Pragma("unroll")                                                         \
        for (int i = 0; i < 2; i++) {                                             \
            int c = tid + i * 256;                                                \
            int r = c >> 2, kq = c & 3;                                           \
            CPASYNC16(as0 + (buf) * AS_BUF_BYTES + (uint32_t)(r * 40 + kq * 8) * 2,\
                      &A[(size_t)(row0 + r) * K + (k0) + kq * 8]);                \
        }                                                                         \
        _Pragma("unroll")                                                         \
        for (int i = 0; i < 2; i++) {                                             \
            int c = tid + i * 256;                                                \
            int kr = c >> 4, nq = c & 15;                                         \
            CPASYNC16(bs0 + (buf) * BS_BUF_BYTES + (uint32_t)(kr * 136 + nq * 8) * 2,\
                      &B[(size_t)((k0) + kr) * N + col0 + nq * 8]);               \
        }                                                                         \
        asm volatile("cp.async.commit_group;");                                   \
    }

    const int nk = K / GBK;
    LOAD_TILE(0, 0)

    for (int it = 0; it < nk; it++) {
        asm volatile("cp.async.wait_group 0;");
        __syncthreads();
        if (it + 1 < nk) LOAD_TILE((it + 1) * GBK, (it + 1) & 1)
        const uint32_t ab = as0 + (it & 1) * AS_BUF_BYTES;
        const uint32_t bbs = bs0 + (it & 1) * BS_BUF_BYTES;

#pragma unroll
        for (int ks = 0; ks < 2; ks++) {
            uint32_t af[4][4], bf[4][2];
#pragma unroll
            for (int mf = 0; mf < 4; mf++)
                LDSM4(af[mf][0], af[mf][1], af[mf][2], af[mf][3],
                      ab + offA[mf] + ks * 32);
            LDSM4T(bf[0][0], bf[0][1], bf[1][0], bf[1][1], bbs + offB0 + ks * 4352);
            LDSM4T(bf[2][0], bf[2][1], bf[3][0], bf[3][1], bbs + offB1 + ks * 4352);
#pragma unroll
            for (int mf = 0; mf < 4; mf++)
#pragma unroll
                for (int nf = 0; nf < 4; nf++)
                    MMA_F16(acc[mf][nf], af[mf][0], af[mf][1], af[mf][2], af[mf][3],
                            bf[nf][0], bf[nf][1]);
        }
        __syncthreads();
    }
#undef LOAD_TILE

    // ---- BN epilogue ----
#pragma unroll
    for (int mf = 0; mf < 4; mf++) {
        int r0 = row0 + wm * 64 + mf * 16 + grp;
        int r1 = r0 + 8;
        float s0 = gg[r0] * rsqrtf(vv[r0] + EPS);
        float h0 = bb[r0] - mm[r0] * s0;
        float s1 = gg[r1] * rsqrtf(vv[r1] + EPS);
        float h1 = bb[r1] - mm[r1] * s1;
#pragma unroll
        for (int nf = 0; nf < 4; nf++) {
            int cc = col0 + wn * 32 + nf * 8 + tig * 2;
            float v00 = acc[mf][nf][0] * s0 + h0;
            float v01 = acc[mf][nf][1] * s0 + h0;
            float v10 = acc[mf][nf][2] * s1 + h1;
            float v11 = acc[mf][nf][3] * s1 + h1;
            if (scatter == 0) {
                *(__half2*)&Ch[(size_t)r0 * N + cc] = __floats2half2_rn(v00, v01);
                *(__half2*)&Ch[(size_t)r1 * N + cc] = __floats2half2_rn(v10, v11);
            } else {
                int b0i = cc / NSP,       sp0 = cc - b0i * NSP;
                int b1i = (cc + 1) / NSP, sp1 = (cc + 1) - b1i * NSP;
                Cf[b0i * (DIM * NSP) + r0 * NSP + sp0] = v00;
                Cf[b1i * (DIM * NSP) + r0 * NSP + sp1] = v01;
                Cf[b0i * (DIM * NSP) + r1 * NSP + sp0] = v10;
                Cf[b1i * (DIM * NSP) + r1 * NSP + sp1] = v11;
            }
        }
    }
}

// ---------------------------------------------------------------------------
// K2: depthwise 3x3 conv + BN (half in, half out)
// ---------------------------------------------------------------------------
__global__ void k_dwconv_bn(const __half* __restrict__ qkv,
                            const float* __restrict__ w,
                            __half* __restrict__ qout,
                            const float* __restrict__ gg, const float* __restrict__ bb,
                            const float* __restrict__ mm, const float* __restrict__ vv)
{
    int i = blockIdx.x * 256 + threadIdx.x;
    if (i >= NH_KD * NTOT) return;
    int sp = i % NSP;
    int b  = (i / NSP) % BATCH;
    int c  = i / NTOT;
    int y = sp / RES, x = sp % RES;

    const __half* base = qkv + (size_t)c * NTOT + b * NSP;
    const float* wc = w + c * 9;
    float acc = 0.f;
#pragma unroll
    for (int dy = -1; dy <= 1; dy++) {
        int yy = y + dy;
        if (yy < 0 || yy >= RES) continue;
#pragma unroll
        for (int dx = -1; dx <= 1; dx++) {
            int xx = x + dx;
            if (xx < 0 || xx >= RES) continue;
            acc = fmaf(wc[(dy + 1) * 3 + (dx + 1)], __half2float(base[yy * RES + xx]), acc);
        }
    }
    float s  = gg[c] * rsqrtf(vv[c] + EPS);
    float sh = bb[c] - mm[c] * s;
    qout[i] = __float2half(acc * s + sh);
}

// ---------------------------------------------------------------------------
// K3: fp16 tensor-core attention, full 128-dv per CTA, 256 threads (8 warps).
//   S^T = K^T x Q (m16n8k16), softmax, O^T = V x P^T with P^T fragments
//   built from S accumulators via shuffles + f32->f16x2 packs.
// ---------------------------------------------------------------------------
#define ATTN_THREADS 256
#define QP 216   // q_s pitch (halfs): 432 B -> ldmatrix trans conflict-free
#define KP 40    // k_s pitch: 80 B -> ldmatrix conflict-free
#define VP 216   // v_s pitch: 432 B
#define Q_OFF 0
#define K_OFF (32*QP*2)                  // 13824
#define V_OFF (K_OFF + 208*KP*2)         // 30464
#define B_OFF (V_OFF + 128*VP*2)         // 85760
#define ATTN_SMEM (B_OFF + 196*4)        // 86544

__global__ __launch_bounds__(ATTN_THREADS, 2) void k_attn(
    const __half* __restrict__ qbuf, const __half* __restrict__ qkv,
    const float* __restrict__ biases, const int* __restrict__ idxs,
    __half* __restrict__ obuf)
{
    extern __shared__ __align__(16) char smraw[];
    __half* q_s = (__half*)(smraw + Q_OFF);   // [d=32][q QP]
    __half* k_s = (__half*)(smraw + K_OFF);   // [m=208][d KP]
    __half* v_s = (__half*)(smraw + V_OFF);   // [dv=128][m VP]
    float*  b_s = (float*) (smraw + B_OFF);   // [196]
    const uint32_t sbase = (uint32_t)__cvta_generic_to_shared(smraw);

    const int bh = blockIdx.x, b = bh >> 3, h = bh & 7;
    const int tid = threadIdx.x;
    const size_t gbase = (size_t)b * NSP;

    // ---- zero pads ----
    for (int i = tid; i < 32 * 10; i += ATTN_THREADS)       // q cols 196..215
        *(__half2*)&q_s[(i / 10) * QP + 196 + (i % 10) * 2] = __half2(__float2half(0.f), __float2half(0.f));
    for (int i = tid; i < 12 * (KP / 2); i += ATTN_THREADS) // k rows 196..207
        *(__half2*)&k_s[(196 + i / (KP / 2)) * KP + (i % (KP / 2)) * 2] = __half2(__float2half(0.f), __float2half(0.f));
    for (int i = tid; i < 128 * 10; i += ATTN_THREADS)      // v cols 196..215
        *(__half2*)&v_s[(i / 10) * VP + 196 + (i % 10) * 2] = __half2(__float2half(0.f), __float2half(0.f));

    // ---- loads ----
    for (int i = tid; i < 32 * 98; i += ATTN_THREADS) {     // q rows (vector)
        int d = i / 98, m2 = i % 98;
        *(__half2*)&q_s[d * QP + m2 * 2] =
            *(const __half2*)&qbuf[(size_t)(h * 32 + d) * NTOT + gbase + m2 * 2];
    }
    for (int i = tid; i < 32 * 196; i += ATTN_THREADS) {    // k transposed (scalar)
        int d = i / 196, m = i % 196;
        k_s[m * KP + d] = qkv[(size_t)(NH_KD + h * 32 + d) * NTOT + gbase + m];
    }
    for (int i = tid; i < 128 * 98; i += ATTN_THREADS) {    // v rows (vector)
        int d = i / 98, m2 = i % 98;
        *(__half2*)&v_s[d * VP + m2 * 2] =
            *(const __half2*)&qkv[(size_t)(2 * NH_KD + h * 128 + d) * NTOT + gbase + m2 * 2];
    }
    for (int i = tid; i < 196; i += ATTN_THREADS) b_s[i] = biases[h * NSP + i];
    __syncthreads();

    const int warp = tid >> 5, lane = tid & 31, grp = lane >> 2, tig = lane & 3;
    const float scale = 0.17677669529663687f;

    // lane-dependent ldmatrix offsets
    const uint32_t qoffL = Q_OFF + (uint32_t)(((lane & 7) + ((lane & 8) ? 8 : 0)) * QP) * 2;
    const uint32_t koffL = K_OFF + (uint32_t)((lane & 15) * KP + ((lane & 16) ? 8 : 0)) * 2;
    uint32_t voffL[8];
#pragma unroll
    for (int dt = 0; dt < 8; dt++)
        voffL[dt] = V_OFF + (uint32_t)((dt * 16 + (lane & 15)) * VP + ((lane & 16) ? 8 : 0)) * 2;

    for (int s = warp; s < 26; s += 8) {
        const int q0 = s * 8;

        // ---- Q B-fragments (2 k-steps of d) ----
        uint32_t qf[2][2];
#pragma unroll
        for (int ks = 0; ks < 2; ks++)
            LDSM2T(qf[ks][0], qf[ks][1], sbase + qoffL + (uint32_t)(ks * 16 * QP + q0) * 2);

        // ---- S^T = K^T x Q ----
        float sc[13][4];
#pragma unroll
        for (int T = 0; T < 13; T++) { sc[T][0]=sc[T][1]=sc[T][2]=sc[T][3]=0.f; }
#pragma unroll
        for (int T = 0; T < 13; T++) {
#pragma unroll
            for (int ks = 0; ks < 2; ks++) {
                uint32_t a0, a1, a2, a3;
                LDSM4(a0, a1, a2, a3,
                      sbase + koffL + (uint32_t)(T * 16 * KP + ks * 16) * 2);
                MMA_F16(sc[T], a0, a1, a2, a3, qf[ks][0], qf[ks][1]);
            }
        }

        // ---- scale + bias + mask; rowwise max over keys ----
        const int qa = q0 + 2 * tig, qb = qa + 1;
        const bool qv = qa < 196;
        const int qaC = qv ? qa : 0;
        const int qbC = qv ? qb : 0;
        float mx0 = -1e30f, mx1 = -1e30f;
#pragma unroll
        for (int T = 0; T < 13; T++) {
            int k0 = T * 16 + grp, k1 = k0 + 8;
            int k0C = (k0 < 196) ? k0 : 0;
            int k1C = (k1 < 196) ? k1 : 0;
            float b00 = b_s[__ldg(&idxs[qaC * NSP + k0C])];
            float b01 = b_s[__ldg(&idxs[qbC * NSP + k0C])];
            float b10 = b_s[__ldg(&idxs[qaC * NSP + k1C])];
            float b11 = b_s[__ldg(&idxs[qbC * NSP + k1C])];
            sc[T][0] = (k0 < 196 && qv) ? sc[T][0] * scale + b00 : -1e30f;
            sc[T][1] = (k0 < 196 && qv) ? sc[T][1] * scale + b01 : -1e30f;
            sc[T][2] = (k1 < 196 && qv) ? sc[T][2] * scale + b10 : -1e30f;
            sc[T][3] = (k1 < 196 && qv) ? sc[T][3] * scale + b11 : -1e30f;
            mx0 = fmaxf(mx0, fmaxf(sc[T][0], sc[T][2]));
            mx1 = fmaxf(mx1, fmaxf(sc[T][1], sc[T][3]));
        }
#pragma unroll
        for (int off = 4; off <= 16; off <<= 1) {
            mx0 = fmaxf(mx0, __shfl_xor_sync(0xFFFFFFFFu, mx0, off));
            mx1 = fmaxf(mx1, __shfl_xor_sync(0xFFFFFFFFu, mx1, off));
        }
        float sum0 = 0.f, sum1 = 0.f;
#pragma unroll
        for (int T = 0; T < 13; T++) {
            sc[T][0] = __expf(sc[T][0] - mx0); sum0 += sc[T][0];
            sc[T][1] = __expf(sc[T][1] - mx1); sum1 += sc[T][1];
            sc[T][2] = __expf(sc[T][2] - mx0); sum0 += sc[T][2];
            sc[T][3] = __expf(sc[T][3] - mx1); sum1 += sc[T][3];
        }
#pragma unroll
        for (int off = 4; off <= 16; off <<= 1) {
            sum0 += __shfl_xor_sync(0xFFFFFFFFu, sum0, off);
            sum1 += __shfl_xor_sync(0xFFFFFFFFu, sum1, off);
        }

        // ---- O^T = V x P^T ----
        float o[8][4];
#pragma unroll
        for (int dt = 0; dt < 8; dt++) { o[dt][0]=o[dt][1]=o[dt][2]=o[dt][3]=0.f; }

        const int LA = 8 * tig + (grp >> 1);   // src lane for m = 2*tig (and +8)
        const int LB = LA + 4;                 // src lane for m = 2*tig+1 (and +9)
        const bool odd = (grp & 1);
#pragma unroll
        for (int T = 0; T < 13; T++) {
            float a0 = __shfl_sync(0xFFFFFFFFu, sc[T][0], LA);
            float a1 = __shfl_sync(0xFFFFFFFFu, sc[T][1], LA);
            float a2 = __shfl_sync(0xFFFFFFFFu, sc[T][2], LA);
            float a3 = __shfl_sync(0xFFFFFFFFu, sc[T][3], LA);
            float c0 = __shfl_sync(0xFFFFFFFFu, sc[T][0], LB);
            float c1 = __shfl_sync(0xFFFFFFFFu, sc[T][1], LB);
            float c2 = __shfl_sync(0xFFFFFFFFu, sc[T][2], LB);
            float c3 = __shfl_sync(0xFFFFFFFFu, sc[T][3], LB);
            uint32_t pb0 = packh2(odd ? a1 : a0, odd ? c1 : c0);
            uint32_t pb1 = packh2(odd ? a3 : a2, odd ? c3 : c2);
#pragma unroll
            for (int dt = 0; dt < 8; dt++) {
                uint32_t v0, v1, v2, v3;
                LDSM4(v0, v1, v2, v3, sbase + voffL[dt] + (uint32_t)(T * 16) * 2);
                MMA_F16(o[dt], v0, v1, v2, v3, pb0, pb1);
            }
        }

        // ---- normalize + ReLU + store (half2) ----
        if (qv) {
            float inv0 = 1.f / sum0, inv1 = 1.f / sum1;
#pragma unroll
            for (int dt = 0; dt < 8; dt++) {
                *(__half2*)&obuf[(size_t)(h * DV + dt * 16 + grp) * NTOT + gbase + qa] =
                    __floats2half2_rn(fmaxf(o[dt][0] * inv0, 0.f), fmaxf(o[dt][1] * inv1, 0.f));
                *(__half2*)&obuf[(size_t)(h * DV + dt * 16 + grp + 8) * NTOT + gbase + qa] =
                    __floats2half2_rn(fmaxf(o[dt][2] * inv0, 0.f), fmaxf(o[dt][3] * inv1, 0.f));
            }
        }
    }
}

// ---------------------------------------------------------------------------
// launch
// ---------------------------------------------------------------------------
extern "C" void kernel_launch(void* const* d_in, const int* in_sizes, int n_in,
                              void* d_out, int out_size)
{
    const float* x      = (const float*)d_in[0];
    const float* qkv_w  = (const float*)d_in[1];
    const float* qkv_g  = (const float*)d_in[2];
    const float* qkv_b  = (const float*)d_in[3];
    const float* qkv_m  = (const float*)d_in[4];
    const float* qkv_v  = (const float*)d_in[5];
    const float* dw_w   = (const float*)d_in[6];
    const float* dw_g   = (const float*)d_in[7];
    const float* dw_b   = (const float*)d_in[8];
    const float* dw_m   = (const float*)d_in[9];
    const float* dw_v   = (const float*)d_in[10];
    const float* proj_w = (const float*)d_in[11];
    const float* proj_g = (const float*)d_in[12];
    const float* proj_b = (const float*)d_in[13];
    const float* proj_m = (const float*)d_in[14];
    const float* proj_v = (const float*)d_in[15];
    const float* ab     = (const float*)d_in[16];
    const int*   idxs   = (const int*)  d_in[17];
    float* out = (float*)d_out;

    __half *xT, *qkvb, *qb, *ob, *wq, *wp;
    cudaGetSymbolAddress((void**)&xT,   g_xT);
    cudaGetSymbolAddress((void**)&qkvb, g_qkv);
    cudaGetSymbolAddress((void**)&qb,   g_q);
    cudaGetSymbolAddress((void**)&ob,   g_o);
    cudaGetSymbolAddress((void**)&wq,   g_wq);
    cudaGetSymbolAddress((void**)&wp,   g_wp);

    cudaFuncSetAttribute(k_attn, cudaFuncAttributeMaxDynamicSharedMemorySize, ATTN_SMEM);

    // weight conversions
    k_f2h<<<(H_QKV * DIM + 255) / 256, 256>>>(qkv_w, wq, H_QKV * DIM);
    k_f2h<<<(DIM * DH + 255) / 256, 256>>>(proj_w, wp, DIM * DH);

    // transpose x -> half
    k_transpose<<<(DIM * NTOT + 255) / 256, 256>>>(x, xT);

    // qkv GEMM + BN (M=1536, N=50176, K=384) -> half
    {
        dim3 grid(H_QKV / GBM, NTOT / GBN);
        k_gemm_f16<<<grid, 256>>>(wq, xT, qkvb, nullptr, H_QKV, NTOT, DIM,
                                  qkv_g, qkv_b, qkv_m, qkv_v, 0);
    }

    // depthwise conv + BN
    k_dwconv_bn<<<(NH_KD * NTOT + 255) / 256, 256>>>(qkvb, dw_w, qb,
                                                     dw_g, dw_b, dw_m, dw_v);

    // attention (+ ReLU) -> half
    k_attn<<<BATCH * HEADS, ATTN_THREADS, ATTN_SMEM>>>(qb, qkvb, ab, idxs, ob);

    // proj GEMM + BN -> fp32 scatter to [B, 384, 14, 14]
    {
        dim3 grid(DIM / GBM, NTOT / GBN);
        k_gemm_f16<<<grid, 256>>>(wp, ob, nullptr, out, DIM, NTOT, DH,
                                  proj_g, proj_b, proj_m, proj_v, 1);
    }
}